// round 14
// baseline (speedup 1.0000x reference)
#include <cuda_runtime.h>
#include <cuda_bf16.h>
#include <cstddef>

#define RR   7
#define KS   15            // 2R+1
#define NK   (KS*KS)       // 225
#define BATCH 8
#define HI   512
#define WI   512
#define HO   256
#define WO   256
#define TY   4             // output rows per block
#define SEG  148           // per-warp smem segment: 128 cols + 19 halo + 1
#define SEGP 152           // padded (16B-aligned: 152*4=608)
#define NBLK (BATCH * (HO/TY) * KS)   // 8*64*15 = 7680
#define DYN_SMEM 46080     // caps occupancy at 4 CTAs/SM (4*46080=184KB <= 228KB)

__global__ __launch_bounds__(256)
void adj_equality_kernel(const float* __restrict__ in, float* __restrict__ out)
{
    extern __shared__ float nb[];   // 8 warps * SEGP floats used

    // item decode: (dy, b, ytile) with SPATIAL index fastest ->
    // concurrent blocks sweep each dx-plane sequentially in y (page locality)
    const int item = blockIdx.x;
    const int sp   = item & 511;         // 0..511  (b,ytile) fastest
    const int dy   = item >> 9;          // 0..14
    const int yt   = sp & 63;            // 0..63
    const int b    = sp >> 6;            // 0..7
    const int y0   = yt * TY;

    const int tid  = threadIdx.x;
    const int wid  = tid >> 5;           // 0..7
    const int lane = tid & 31;
    const int ty   = wid >> 1;           // 0..3 (row group)
    const int h    = wid & 1;            // half-row: 0 or 1
    const int cb   = h * 128;            // column base of this warp's segment
    const int lx   = cb + lane * 4;      // output column base (0..252)

    const float* __restrict__ inb = in + (size_t)b * HI * WI;
    float* __restrict__ wseg = nb + wid * SEGP;

    // ---- Per-warp fill: this warp's 148-col halo segment of neighbor row ----
    // smem local index i <-> global gx = cb + i - RR
    {
        const int ny = y0 + ty + dy - RR;
        const bool yok = (ny >= 0) && (ny < HO);
        const float* __restrict__ irow = inb + (size_t)(ny * 2) * WI;
        #pragma unroll
        for (int k = 0; k < 5; ++k) {    // 5*32 = 160 >= 148
            const int i = lane + k * 32;
            if (i < SEG) {
                const int gx = cb + i - RR;
                float v = 0.0f;
                if (yok && gx >= 0 && gx < WO)
                    v = irow[(size_t)(gx * 2)];
                wseg[i] = v;
            }
        }
    }

    // ---- Centers straight from global (L2-hot) ----
    const int y = y0 + ty;
    const float* __restrict__ crow = inb + (size_t)(y * 2) * WI;
    const float c0 = crow[(size_t)((lx + 0) * 2)];
    const float c1 = crow[(size_t)((lx + 1) * 2)];
    const float c2 = crow[(size_t)((lx + 2) * 2)];
    const float c3 = crow[(size_t)((lx + 3) * 2)];

    __syncwarp();   // only intra-warp visibility needed: warp reads its own segment

    // ---- Register window: 20 floats via 5x LDS.128 (16B-aligned) ----
    // window for output x=lx..lx+3 + dx needs gx = lx-7 .. lx+12+3
    //   = local indices (lx-cb) .. (lx-cb)+19  (lane*4, 16B aligned)
    const float4* __restrict__ wrow =
        reinterpret_cast<const float4*>(wseg + lane * 4);
    float w[20];
    #pragma unroll
    for (int q = 0; q < 5; ++q) {
        const float4 v = wrow[q];
        w[q * 4 + 0] = v.x;
        w[q * 4 + 1] = v.y;
        w[q * 4 + 2] = v.z;
        w[q * 4 + 3] = v.w;
    }

    float* __restrict__ outp = out + ((size_t)b * NK + (size_t)(dy * KS)) * HO * WO
                                   + (size_t)y * WO + lx;

    #pragma unroll
    for (int dx = 0; dx < KS; ++dx) {
        float4 v;
        v.x = (w[dx + 0] == c0) ? 1.0f : 0.0f;
        v.y = (w[dx + 1] == c1) ? 1.0f : 0.0f;
        v.z = (w[dx + 2] == c2) ? 1.0f : 0.0f;
        v.w = (w[dx + 3] == c3) ? 1.0f : 0.0f;
        // streaming store hint: evict-first dirty lines -> steadier L2->DRAM drain
        __stcs(reinterpret_cast<float4*>(outp + (size_t)dx * HO * WO), v);
    }
}

extern "C" void kernel_launch(void* const* d_in, const int* in_sizes, int n_in,
                              void* d_out, int out_size)
{
    const float* segments = (const float*)d_in[0];
    float* out = (float*)d_out;

    adj_equality_kernel<<<NBLK, 256, DYN_SMEM>>>(segments, out);
}